// round 11
// baseline (speedup 1.0000x reference)
#include <cuda_runtime.h>
#include <cuda_bf16.h>

// PyramidROIAlign R11: prep resolves ABSOLUTE corner-00 addresses (level/batch
// select + all address arithmetic moved out of the hot loop). Gather inner
// loop: 2 broadcast param loads -> 3 IADD -> 4x LDG.128 -> 16 FFMA -> STG.128.

#define POOL_W 7
#define NCELLS 49
#define NCH    256
#define NBOXES 1000
#define NBATCH 2
#define NTASKS (NBATCH * NBOXES * NCELLS)      // 98000
#define CELLS_PER_GROUP 4
#define TASKS_PER_BLOCK (4 * CELLS_PER_GROUP)  // 16; 98000 = 6125 * 16

struct __align__(16) CellParam {
    unsigned long long addr00;  // absolute byte address of corner (y0,x0), channel 0
    int   d01, d10;             // byte deltas: +x1 column, +y1 row  (d11 = d01+d10)
    float a00, a01, a10, a11;   // bilinear weights * validity
};

__device__ CellParam g_cp[NTASKS];

__global__ __launch_bounds__(256) void prep_kernel(
    const float* __restrict__ boxes,
    const float* __restrict__ p3,
    const float* __restrict__ p4,
    const float* __restrict__ p5)
{
    const int id = blockIdx.x * 256 + threadIdx.x;
    if (id >= NTASKS) return;

    const int box  = id / NCELLS;
    const int cell = id - box * NCELLS;
    const int b    = (box >= NBOXES) ? 1 : 0;

    const float y1 = __ldg(boxes + box * 4 + 0);
    const float x1 = __ldg(boxes + box * 4 + 1);
    const float y2 = __ldg(boxes + box * 4 + 2);
    const float x2 = __ldg(boxes + box * 4 + 3);
    const float h  = y2 - y1;
    const float w  = x2 - x1;

    float lvlf = ceilf(5.0f + logf(h * w) / 0.6931471805599453f);
    lvlf = fminf(fmaxf(lvlf, 3.0f), 5.0f);
    const int level = (int)lvlf;

    const float* feat;
    int HW;
    if (level == 3)      { feat = p3; HW = 128; }
    else if (level == 4) { feat = p4; HW = 64;  }
    else                 { feat = p5; HW = 32;  }

    const float Hm1 = (float)(HW - 1);
    const int   iy  = cell / POOL_W;
    const int   ix  = cell - iy * POOL_W;
    // exact reference rounding order for all discrete decisions
    const float stepy = __fdiv_rn(__fmul_rn(h, Hm1), 6.0f);
    const float stepx = __fdiv_rn(__fmul_rn(w, Hm1), 6.0f);
    const float ys = __fadd_rn(__fmul_rn(y1, Hm1), __fmul_rn((float)iy, stepy));
    const float xs = __fadd_rn(__fmul_rn(x1, Hm1), __fmul_rn((float)ix, stepx));

    const bool  valid = (ys >= 0.0f) & (ys <= Hm1) & (xs >= 0.0f) & (xs <= Hm1);
    const float vm = valid ? 1.0f : 0.0f;

    const float y0f = floorf(ys);
    const float x0f = floorf(xs);
    const float wy  = ys - y0f;
    const float wx  = xs - x0f;
    const float owy = 1.0f - wy;
    const float owx = 1.0f - wx;

    const int y0i = (int)fminf(fmaxf(y0f, 0.0f), Hm1);
    const int y1i = (int)fminf(fmaxf(y0f + 1.0f, 0.0f), Hm1);
    const int x0i = (int)fminf(fmaxf(x0f, 0.0f), Hm1);
    const int x1i = (int)fminf(fmaxf(x0f + 1.0f, 0.0f), Hm1);

    const int rowbytes = HW * NCH * 4;

    CellParam p;
    p.addr00 = (unsigned long long)(const char*)feat
             + (unsigned long long)(b * HW * HW * NCH * 4)
             + (unsigned long long)(y0i * rowbytes + x0i * (NCH * 4));
    p.d01 = (x1i - x0i) * (NCH * 4);
    p.d10 = (y1i - y0i) * rowbytes;
    p.a00 = owx * owy * vm;
    p.a01 = wx  * owy * vm;
    p.a10 = owx * wy  * vm;
    p.a11 = wx  * wy  * vm;
    g_cp[id] = p;
}

__global__ __launch_bounds__(256) void gather_kernel(float* __restrict__ out)
{
    const int local = threadIdx.x >> 6;          // group 0..3
    const int lane  = threadIdx.x & 63;          // float4 channel group
    const int base  = blockIdx.x * TASKS_PER_BLOCK + local * CELLS_PER_GROUP;
    const long laneoff = lane * 16;

    #pragma unroll 2
    for (int i = 0; i < CELLS_PER_GROUP; i++) {
        const int pt = base + i;

        // params: two broadcast 16B loads (L1-resident)
        const ulonglong2 pa = __ldg((const ulonglong2*)&g_cp[pt]);     // addr00, (d01,d10)
        const float4     aa = __ldg((const float4*)((const char*)&g_cp[pt] + 16));

        const char* a00p = (const char*)pa.x + laneoff;
        const int   d01  = (int)(pa.y & 0xffffffffull);
        const int   d10  = (int)(pa.y >> 32);

        const float4 v00 = __ldg((const float4*)(a00p));
        const float4 v01 = __ldg((const float4*)(a00p + d01));
        const float4 v10 = __ldg((const float4*)(a00p + d10));
        const float4 v11 = __ldg((const float4*)(a00p + d01 + d10));

        float4 o;
        o.x = v00.x * aa.x + v01.x * aa.y + v10.x * aa.z + v11.x * aa.w;
        o.y = v00.y * aa.x + v01.y * aa.y + v10.y * aa.z + v11.y * aa.w;
        o.z = v00.z * aa.x + v01.z * aa.y + v10.z * aa.z + v11.z * aa.w;
        o.w = v00.w * aa.x + v01.w * aa.y + v10.w * aa.z + v11.w * aa.w;

        __stcs((float4*)out + (size_t)pt * 64 + lane, o);
    }
}

extern "C" void kernel_launch(void* const* d_in, const int* in_sizes, int n_in,
                              void* d_out, int out_size) {
    const float* boxes = (const float*)d_in[0];
    const float* p3    = (const float*)d_in[2];
    const float* p4    = (const float*)d_in[3];
    const float* p5    = (const float*)d_in[4];
    float* out = (float*)d_out;

    prep_kernel<<<(NTASKS + 255) / 256, 256>>>(boxes, p3, p4, p5);
    gather_kernel<<<NTASKS / TASKS_PER_BLOCK, 256>>>(out);
}

// round 12
// speedup vs baseline: 1.1096x; 1.1096x over previous
#include <cuda_runtime.h>
#include <cuda_bf16.h>

// PyramidROIAlign R12: fused fine-grained single kernel.
// 6125 blocks x 256 threads, 16 (box,cell) tasks per block.
// Phase 1 (threads 0..15): per-task params -> absolute corner-00 address,
//   row/col byte deltas, bilinear weights*validity (exact reference rounding
//   for all discrete decisions). 512B smem.
// Phase 2: 4 groups x 64 float4-lanes, 4 cells each:
//   LDS params -> 1 IADD64 + 2 IADD -> 4x LDG.128 -> 16 FFMA -> STG.128(cs).

#define POOL_W 7
#define NCELLS 49
#define NCH    256
#define NBOXES 1000
#define NBATCH 2
#define NTASKS (NBATCH * NBOXES * NCELLS)      // 98000
#define CELLS_PER_GROUP 4
#define TASKS_PER_BLOCK 16                      // 98000 = 6125 * 16

struct __align__(16) CellParam {
    unsigned long long addr00;  // absolute byte address of corner (y0,x0), channel 0
    int   d01, d10;             // byte deltas: +x1 column, +y1 row (d11 = d01+d10)
    float a00, a01, a10, a11;   // bilinear weights * validity
};

__global__ __launch_bounds__(256) void pyramid_roi_align_kernel(
    const float* __restrict__ boxes,
    const float* __restrict__ p3,      // [B,128,128,C]
    const float* __restrict__ p4,      // [B,64,64,C]
    const float* __restrict__ p5,      // [B,32,32,C]
    float* __restrict__ out)           // [B*N, 7, 7, C]
{
    __shared__ CellParam cp[TASKS_PER_BLOCK];

    const int tid   = threadIdx.x;
    const int tbase = blockIdx.x * TASKS_PER_BLOCK;

    // ---- phase 1: threads 0..15 compute one task's params each ----
    if (tid < TASKS_PER_BLOCK) {
        const int id   = tbase + tid;
        const int box  = id / NCELLS;
        const int cell = id - box * NCELLS;
        const int b    = (box >= NBOXES) ? 1 : 0;

        const float y1 = __ldg(boxes + box * 4 + 0);
        const float x1 = __ldg(boxes + box * 4 + 1);
        const float y2 = __ldg(boxes + box * 4 + 2);
        const float x2 = __ldg(boxes + box * 4 + 3);
        const float h  = y2 - y1;
        const float w  = x2 - x1;

        float lvlf = ceilf(5.0f + logf(h * w) / 0.6931471805599453f);
        lvlf = fminf(fmaxf(lvlf, 3.0f), 5.0f);
        const int level = (int)lvlf;

        const float* feat;
        int HW;
        if (level == 3)      { feat = p3; HW = 128; }
        else if (level == 4) { feat = p4; HW = 64;  }
        else                 { feat = p5; HW = 32;  }

        const float Hm1 = (float)(HW - 1);
        const int   iy  = cell / POOL_W;
        const int   ix  = cell - iy * POOL_W;
        // exact reference rounding order for all discrete decisions
        const float stepy = __fdiv_rn(__fmul_rn(h, Hm1), 6.0f);
        const float stepx = __fdiv_rn(__fmul_rn(w, Hm1), 6.0f);
        const float ys = __fadd_rn(__fmul_rn(y1, Hm1), __fmul_rn((float)iy, stepy));
        const float xs = __fadd_rn(__fmul_rn(x1, Hm1), __fmul_rn((float)ix, stepx));

        const bool  valid = (ys >= 0.0f) & (ys <= Hm1) & (xs >= 0.0f) & (xs <= Hm1);
        const float vm = valid ? 1.0f : 0.0f;

        const float y0f = floorf(ys);
        const float x0f = floorf(xs);
        const float wy  = ys - y0f;
        const float wx  = xs - x0f;
        const float owy = 1.0f - wy;
        const float owx = 1.0f - wx;

        const int y0i = (int)fminf(fmaxf(y0f, 0.0f), Hm1);
        const int y1i = (int)fminf(fmaxf(y0f + 1.0f, 0.0f), Hm1);
        const int x0i = (int)fminf(fmaxf(x0f, 0.0f), Hm1);
        const int x1i = (int)fminf(fmaxf(x0f + 1.0f, 0.0f), Hm1);

        const int rowbytes = HW * NCH * 4;

        CellParam p;
        p.addr00 = (unsigned long long)(const char*)feat
                 + (unsigned long long)(b * HW * HW * NCH * 4)
                 + (unsigned long long)(y0i * rowbytes + x0i * (NCH * 4));
        p.d01 = (x1i - x0i) * (NCH * 4);
        p.d10 = (y1i - y0i) * rowbytes;
        p.a00 = owx * owy * vm;
        p.a01 = wx  * owy * vm;
        p.a10 = owx * wy  * vm;
        p.a11 = wx  * wy  * vm;
        cp[tid] = p;
    }
    __syncthreads();

    // ---- phase 2: 4 groups x 64 lanes; 4 cells per group ----
    const int local = tid >> 6;                  // group 0..3
    const int lane  = tid & 63;                  // float4 channel group
    const long laneoff = lane * 16;
    const int  slot0   = local * CELLS_PER_GROUP;

    #pragma unroll 2
    for (int i = 0; i < CELLS_PER_GROUP; i++) {
        const int slot = slot0 + i;

        const ulonglong2 pa = ((const ulonglong2*)&cp[slot])[0];   // addr00, (d01,d10)
        const float4     aa = ((const float4*)&cp[slot])[1];

        const char* a00p = (const char*)pa.x + laneoff;
        const int   d01  = (int)(pa.y & 0xffffffffull);
        const int   d10  = (int)(pa.y >> 32);

        const float4 v00 = __ldg((const float4*)(a00p));
        const float4 v01 = __ldg((const float4*)(a00p + d01));
        const float4 v10 = __ldg((const float4*)(a00p + d10));
        const float4 v11 = __ldg((const float4*)(a00p + d01 + d10));

        float4 o;
        o.x = v00.x * aa.x + v01.x * aa.y + v10.x * aa.z + v11.x * aa.w;
        o.y = v00.y * aa.x + v01.y * aa.y + v10.y * aa.z + v11.y * aa.w;
        o.z = v00.z * aa.x + v01.z * aa.y + v10.z * aa.z + v11.z * aa.w;
        o.w = v00.w * aa.x + v01.w * aa.y + v10.w * aa.z + v11.w * aa.w;

        __stcs((float4*)out + (size_t)(tbase + slot) * 64 + lane, o);
    }
}

extern "C" void kernel_launch(void* const* d_in, const int* in_sizes, int n_in,
                              void* d_out, int out_size) {
    const float* boxes = (const float*)d_in[0];
    const float* p3    = (const float*)d_in[2];
    const float* p4    = (const float*)d_in[3];
    const float* p5    = (const float*)d_in[4];
    float* out = (float*)d_out;

    pyramid_roi_align_kernel<<<NTASKS / TASKS_PER_BLOCK, 256>>>(boxes, p3, p4, p5, out);
}